// round 2
// baseline (speedup 1.0000x reference)
#include <cuda_runtime.h>

#define NDIM 4096
#define TPB  256
#define F4PT 4   // float4 per thread -> 16 elements/thread

__device__ unsigned short g_lab[NDIM];
__device__ double g_acc;

// Labels may arrive as int32 (JAX canonicalizes int64->int32 without x64) or
// genuine int64. Detect: int64 little-endian values <512 have all-zero high
// words at odd int32 indices; for int32 data P(first 32 odd labels all zero)
// = 512^-32 ~= 0. Deterministic given the input.
__global__ void prep_kernel(const int* __restrict__ labels32) {
    __shared__ int is64;
    if (threadIdx.x == 0) {
        int z = 1;
        #pragma unroll
        for (int k = 1; k < 64; k += 2)
            if (labels32[k] != 0) { z = 0; break; }
        is64 = z;
    }
    __syncthreads();
    int t = blockIdx.x * blockDim.x + threadIdx.x;
    if (t < NDIM) {
        int v = is64 ? labels32[2 * t] : labels32[t];
        g_lab[t] = (unsigned short)v;
    }
    if (t == 0) g_acc = 0.0;
}

__device__ __forceinline__ float blockMax(float v, float* s) {
    #pragma unroll
    for (int o = 16; o; o >>= 1) v = fmaxf(v, __shfl_xor_sync(0xffffffffu, v, o));
    if ((threadIdx.x & 31) == 0) s[threadIdx.x >> 5] = v;
    __syncthreads();
    float r = s[0];
    #pragma unroll
    for (int k = 1; k < TPB / 32; k++) r = fmaxf(r, s[k]);
    __syncthreads();
    return r;
}

__device__ __forceinline__ float blockSum(float v, float* s) {
    #pragma unroll
    for (int o = 16; o; o >>= 1) v += __shfl_xor_sync(0xffffffffu, v, o);
    if ((threadIdx.x & 31) == 0) s[threadIdx.x >> 5] = v;
    __syncthreads();
    float r = 0.f;
    #pragma unroll
    for (int k = 0; k < TPB / 32; k++) r += s[k];
    __syncthreads();
    return r;
}

__global__ __launch_bounds__(TPB) void loss_kernel(const float* __restrict__ logits) {
    __shared__ float sred[TPB / 32];
    const int i = blockIdx.x;
    const int t = threadIdx.x;
    const float SCALE = 7.3890560989306495f;  // exp(2.0) rounded to fp32

    // ---- load row into registers (coalesced float4) ----
    const float4* row4 = reinterpret_cast<const float4*>(logits + (size_t)i * NDIM);
    float4 z[F4PT];
    #pragma unroll
    for (int k = 0; k < F4PT; k++) z[k] = row4[k * TPB + t];

    // ---- pass 1: scale + row max ----
    float m = -1e30f;
    #pragma unroll
    for (int k = 0; k < F4PT; k++) {
        z[k].x *= SCALE; z[k].y *= SCALE; z[k].z *= SCALE; z[k].w *= SCALE;
        m = fmaxf(m, fmaxf(fmaxf(z[k].x, z[k].y), fmaxf(z[k].z, z[k].w)));
    }
    m = blockMax(m, sred);

    // ---- pass 2: exp + sumexp (registers only); capture diagonal d = z_ii - m ----
    float S = 0.f;
    float d_diag = 0.f;
    #pragma unroll
    for (int k = 0; k < F4PT; k++) {
        int j0 = 4 * (k * TPB + t);
        float d0 = z[k].x - m, d1 = z[k].y - m, d2 = z[k].z - m, d3 = z[k].w - m;
        if (j0 == i)          d_diag = d0;
        else if (j0 + 1 == i) d_diag = d1;
        else if (j0 + 2 == i) d_diag = d2;
        else if (j0 + 3 == i) d_diag = d3;
        z[k].x = __expf(d0); z[k].y = __expf(d1);
        z[k].z = __expf(d2); z[k].w = __expf(d3);
        S += (z[k].x + z[k].y) + (z[k].z + z[k].w);
    }
    S = blockSum(S, sred);
    const float invS = 1.0f / S;
    const float logS = logf(S);
    const unsigned int mylab = (unsigned int)g_lab[i];

    // ---- pass 3: masked log1p(-p) + diagonal log p_ii ----
    float acc = 0.f;
    #pragma unroll
    for (int k = 0; k < F4PT; k++) {
        int j0 = 4 * (k * TPB + t);
        uint2 lu = *reinterpret_cast<const uint2*>(g_lab + j0);
        unsigned int labs[4] = { lu.x & 0xFFFFu, lu.x >> 16, lu.y & 0xFFFFu, lu.y >> 16 };
        float es[4] = { z[k].x, z[k].y, z[k].z, z[k].w };
        #pragma unroll
        for (int c = 0; c < 4; c++) {
            int j = j0 + c;
            if (j == i) {
                acc += d_diag - logS;           // log p_ii = (z_ii - m) - log S
            } else if (labs[c] != mylab) {
                float e = es[c];
                float p = e * invS;
                float term;
                if (p > 0.125f) {
                    // exact path, rare; clamp against degenerate S-e==0
                    term = logf(fmaxf((S - e) * invS, 1e-37f));
                } else {
                    // log1p(-p) = -p*(1 + p/2 + p^2/3 + p^3/4 + p^4/5 + p^5/6), err < p^7/7
                    float q = fmaf(p, 0.16666667f, 0.2f);
                    q = fmaf(p, q, 0.25f);
                    q = fmaf(p, q, 0.33333334f);
                    q = fmaf(p, q, 0.5f);
                    q = fmaf(p, q, 1.0f);
                    term = -p * q;
                }
                acc += term;
            }
        }
    }
    acc = blockSum(acc, sred);
    if (t == 0) atomicAdd(&g_acc, (double)acc);
}

__global__ void fin_kernel(float* __restrict__ out) {
    out[0] = (float)(g_acc * (1.0 / (double)NDIM));
}

extern "C" void kernel_launch(void* const* d_in, const int* in_sizes, int n_in,
                              void* d_out, int out_size) {
    const float* logits  = (const float*)d_in[0];
    const int* labels32  = (const int*)d_in[1];
    float* out           = (float*)d_out;

    prep_kernel<<<(NDIM + TPB - 1) / TPB, TPB>>>(labels32);
    loss_kernel<<<NDIM, TPB>>>(logits);
    fin_kernel<<<1, 1>>>(out);
}